// round 1
// baseline (speedup 1.0000x reference)
#include <cuda_runtime.h>
#include <cuda_bf16.h>

// Problem constants (B=32, S=1024, V=64, H=4096)
#define VOCAB 64
#define HID   4096
#define UOUT  128   // 2*V

// Per-token output index table: out_idx[t] = (scale_idx[t]*t + loc_idx[t]) mod 64
__device__ int g_table[VOCAB];

// ---------------------------------------------------------------------------
// K1: build the 64-entry table.
// One block per token t. net = relu(W1[t,:] + b1) staged in smem, then the
// 128-wide logits = net @ W2 + b2 computed by 8 warps (each owns a 512-wide
// H-slice, each lane accumulates 4 consecutive output columns via float4 LDG).
// ---------------------------------------------------------------------------
__global__ __launch_bounds__(256, 1)
void table_kernel(const float* __restrict__ W1, const float* __restrict__ b1,
                  const float* __restrict__ W2, const float* __restrict__ b2) {
    __shared__ float net[HID];
    __shared__ float partial[8][UOUT];
    __shared__ float logits[UOUT];

    const int t   = blockIdx.x;
    const int tid = threadIdx.x;

    // net[h] = relu(W1[t,h] + b1[h])
    #pragma unroll
    for (int h = tid; h < HID; h += 256) {
        float v = W1[t * HID + h] + b1[h];
        net[h] = v > 0.0f ? v : 0.0f;
    }
    __syncthreads();

    const int warp = tid >> 5;
    const int lane = tid & 31;
    const float4* __restrict__ W2v = reinterpret_cast<const float4*>(W2); // row = 32 float4

    float4 acc = make_float4(0.f, 0.f, 0.f, 0.f);
    const int h0 = warp * (HID / 8);
    #pragma unroll 4
    for (int h = h0; h < h0 + (HID / 8); ++h) {
        float  n = net[h];                 // smem broadcast within warp
        float4 w = W2v[h * 32 + lane];     // coalesced 512B per warp
        acc.x = fmaf(n, w.x, acc.x);
        acc.y = fmaf(n, w.y, acc.y);
        acc.z = fmaf(n, w.z, acc.z);
        acc.w = fmaf(n, w.w, acc.w);
    }
    partial[warp][lane * 4 + 0] = acc.x;
    partial[warp][lane * 4 + 1] = acc.y;
    partial[warp][lane * 4 + 2] = acc.z;
    partial[warp][lane * 4 + 3] = acc.w;
    __syncthreads();

    if (tid < UOUT) {
        float s = b2[tid];
        #pragma unroll
        for (int w = 0; w < 8; ++w) s += partial[w][tid];
        logits[tid] = s;
    }
    __syncthreads();

    if (tid == 0) {
        // jnp.argmax keeps the FIRST max -> strict '>' comparison.
        int   li = 0; float lm = logits[0];
        #pragma unroll
        for (int k = 1; k < VOCAB; ++k) if (logits[k] > lm) { lm = logits[k]; li = k; }
        int   si = 0; float sm = logits[VOCAB];
        #pragma unroll
        for (int k = 1; k < VOCAB; ++k) if (logits[VOCAB + k] > sm) { sm = logits[VOCAB + k]; si = k; }
        // loc = first half, scale = second half (jnp.split order)
        g_table[t] = (si * t + li) & (VOCAB - 1);
    }
}

// ---------------------------------------------------------------------------
// K2: streaming pass. 16 threads per row (one float4 each = 64 floats/row).
// Recover token = index of the 1.0, look up table, emit one-hot row.
// Fully coalesced read + write (8 MB each way).
// ---------------------------------------------------------------------------
__global__ __launch_bounds__(256)
void out_kernel(const float4* __restrict__ in, float4* __restrict__ out) {
    const int gid = blockIdx.x * 256 + threadIdx.x;   // float4 index == row*16 + q
    const int q   = gid & 15;                         // which float4 within the row

    float4 v = in[gid];
    int cand = -1;
    if (v.x > 0.5f) cand = q * 4 + 0;
    if (v.y > 0.5f) cand = q * 4 + 1;
    if (v.z > 0.5f) cand = q * 4 + 2;
    if (v.w > 0.5f) cand = q * 4 + 3;

    // max-reduce across the 16 lanes that share this row
    #pragma unroll
    for (int off = 8; off; off >>= 1)
        cand = max(cand, __shfl_xor_sync(0xFFFFFFFFu, cand, off, 16));

    const int oi = g_table[cand];   // uniform broadcast load

    float4 o = make_float4(0.f, 0.f, 0.f, 0.f);
    if ((oi >> 2) == q) {
        reinterpret_cast<float*>(&o)[oi & 3] = 1.0f;
    }
    out[gid] = o;
}

// ---------------------------------------------------------------------------
// kernel_launch: map inputs by element count (all five sizes are distinct),
// then launch table build + streaming pass on the capture stream.
// ---------------------------------------------------------------------------
extern "C" void kernel_launch(void* const* d_in, const int* in_sizes, int n_in,
                              void* d_out, int out_size) {
    const float* inputs = nullptr;
    const float* W1 = nullptr;
    const float* b1 = nullptr;
    const float* W2 = nullptr;
    const float* b2 = nullptr;

    for (int i = 0; i < n_in; ++i) {
        switch (in_sizes[i]) {
            case 32 * 1024 * 64: inputs = (const float*)d_in[i]; break; // 2097152
            case 64 * 4096:      W1     = (const float*)d_in[i]; break; // 262144
            case 4096:           b1     = (const float*)d_in[i]; break;
            case 4096 * 128:     W2     = (const float*)d_in[i]; break; // 524288
            case 128:            b2     = (const float*)d_in[i]; break;
            default: break;
        }
    }

    table_kernel<<<VOCAB, 256>>>(W1, b1, W2, b2);

    const int n_f4 = (32 * 1024 * 64) / 4;            // 524288 float4
    out_kernel<<<n_f4 / 256, 256>>>(
        reinterpret_cast<const float4*>(inputs),
        reinterpret_cast<float4*>(d_out));
}

// round 2
// speedup vs baseline: 2.4220x; 2.4220x over previous
#include <cuda_runtime.h>
#include <cuda_bf16.h>

// Problem constants (B=32, S=1024, V=64, H=4096)
#define VOCAB   64
#define HID     4096
#define UOUT    128          // 2*V
#define NBLK    128          // H-split blocks
#define HCHUNK  (HID / NBLK) // 32

// Per-token output index table: out_idx[t] = (scale_idx[t]*t + loc_idx[t]) mod 64
__device__ int    g_table[VOCAB];
// Partial logits scratch: part[t][b][u], stored as float4 (u-quads)
__device__ float4 g_part[VOCAB * NBLK * (UOUT / 4)];   // 4 MB

// ---------------------------------------------------------------------------
// K1: partial logits + zero-fill of output.
// Block b owns H-chunk [b*32, b*32+32).
//   net[t][h] = relu(W1[t,h]+b1[h])  (smem, 8 KB)
//   W2 chunk  = W2[h0:h0+32, :]      (smem, 16 KB, contiguous in gmem)
//   part[t][b][u] = sum_h net[t][h]*W2[h][u]
// Also zeroes its 64 KB slice of the output (independent stores, overlapped).
// ---------------------------------------------------------------------------
__global__ __launch_bounds__(256, 1)
void partial_kernel(const float* __restrict__ W1, const float* __restrict__ b1,
                    const float* __restrict__ W2, float4* __restrict__ out_zero) {
    __shared__ float nets[VOCAB * HCHUNK];       // [t][h]
    __shared__ float w2s [HCHUNK * UOUT];        // [h][u]

    const int b   = blockIdx.x;
    const int tid = threadIdx.x;
    const int h0  = b * HCHUNK;

    // --- zero-fill output slice (8 MB total across grid), fire-and-forget ---
    {
        const float4 z = make_float4(0.f, 0.f, 0.f, 0.f);
        float4* dst = out_zero + b * 4096;
        #pragma unroll
        for (int i = 0; i < 16; ++i) dst[tid + i * 256] = z;
    }

    // --- stage net = relu(W1 slice + b1 slice) ---
    // 64 t * 8 float4 = 512 float4 loads
    for (int j = tid; j < VOCAB * (HCHUNK / 4); j += 256) {
        const int t = j >> 3;          // j / 8
        const int f = j & 7;           // float4 within chunk
        float4 w = *reinterpret_cast<const float4*>(W1 + t * HID + h0 + f * 4);
        float4 c = *reinterpret_cast<const float4*>(b1 + h0 + f * 4);
        float* n = &nets[t * HCHUNK + f * 4];
        n[0] = fmaxf(w.x + c.x, 0.f);
        n[1] = fmaxf(w.y + c.y, 0.f);
        n[2] = fmaxf(w.z + c.z, 0.f);
        n[3] = fmaxf(w.w + c.w, 0.f);
    }
    // --- stage W2 chunk: 16 KB contiguous ---
    {
        const float4* src = reinterpret_cast<const float4*>(W2 + h0 * UOUT);
        float4*       dst = reinterpret_cast<float4*>(w2s);
        #pragma unroll
        for (int i = 0; i < 4; ++i) dst[tid + i * 256] = src[tid + i * 256];
    }
    __syncthreads();

    // --- compute: thread owns u-quad uq (lane) and 8 tokens (warp group) ---
    const int uq = tid & 31;           // u-quad 0..31
    const int tg = tid >> 5;           // token group 0..7 -> tokens tg*8..tg*8+7
    const int t0 = tg * 8;

    float4 acc[8];
    #pragma unroll
    for (int i = 0; i < 8; ++i) acc[i] = make_float4(0.f, 0.f, 0.f, 0.f);

    #pragma unroll 4
    for (int h = 0; h < HCHUNK; ++h) {
        const float4 w = reinterpret_cast<const float4*>(&w2s[h * UOUT])[uq];
        #pragma unroll
        for (int i = 0; i < 8; ++i) {
            const float n = nets[(t0 + i) * HCHUNK + h];   // warp-uniform broadcast
            acc[i].x = fmaf(n, w.x, acc[i].x);
            acc[i].y = fmaf(n, w.y, acc[i].y);
            acc[i].z = fmaf(n, w.z, acc[i].z);
            acc[i].w = fmaf(n, w.w, acc[i].w);
        }
    }

    // --- write partials: part[t][b][uq], per-warp coalesced 512B rows ---
    #pragma unroll
    for (int i = 0; i < 8; ++i) {
        g_part[((t0 + i) * NBLK + b) * 32 + uq] = acc[i];
    }
}

// ---------------------------------------------------------------------------
// K2: reduce partials over the 128 blocks, add b2, argmax both halves,
// write g_table[t]. One block per token, 128 threads (4 warps split the
// b-range, lanes own u-quads).
// ---------------------------------------------------------------------------
__global__ __launch_bounds__(128, 1)
void reduce_kernel(const float* __restrict__ b2) {
    __shared__ float red[4][UOUT];
    __shared__ float logits[UOUT];

    const int t    = blockIdx.x;
    const int tid  = threadIdx.x;
    const int warp = tid >> 5;
    const int lane = tid & 31;

    float4 acc = make_float4(0.f, 0.f, 0.f, 0.f);
    const float4* base = &g_part[(t * NBLK) * 32 + lane];
    #pragma unroll 8
    for (int b = warp * 32; b < warp * 32 + 32; ++b) {
        const float4 v = base[b * 32];
        acc.x += v.x; acc.y += v.y; acc.z += v.z; acc.w += v.w;
    }
    red[warp][lane * 4 + 0] = acc.x;
    red[warp][lane * 4 + 1] = acc.y;
    red[warp][lane * 4 + 2] = acc.z;
    red[warp][lane * 4 + 3] = acc.w;
    __syncthreads();

    if (tid < UOUT) {
        logits[tid] = red[0][tid] + red[1][tid] + red[2][tid] + red[3][tid] + b2[tid];
    }
    __syncthreads();

    if (tid == 0) {
        // jnp.argmax keeps the FIRST max -> strict '>' comparison.
        int   li = 0; float lm = logits[0];
        #pragma unroll
        for (int k = 1; k < VOCAB; ++k) if (logits[k] > lm) { lm = logits[k]; li = k; }
        int   si = 0; float sm = logits[VOCAB];
        #pragma unroll
        for (int k = 1; k < VOCAB; ++k) if (logits[VOCAB + k] > sm) { sm = logits[VOCAB + k]; si = k; }
        // loc = first half, scale = second half (jnp.split order)
        g_table[t] = (si * t + li) & (VOCAB - 1);
    }
}

// ---------------------------------------------------------------------------
// K3: scatter pass. Output was pre-zeroed in K1; here each thread reads one
// float4 of the one-hot input and, if it holds the 1.0, directly writes the
// single 1.0f to out[row*64 + table[token]]. No cross-lane ops at all.
// ---------------------------------------------------------------------------
__global__ __launch_bounds__(256)
void scatter_kernel(const float4* __restrict__ in, float* __restrict__ out) {
    const int gid = blockIdx.x * 256 + threadIdx.x;   // f4 index = row*16 + q
    const int q   = gid & 15;
    const int row = gid >> 4;

    const float4 v = in[gid];
    int cand = -1;
    if (v.x > 0.5f) cand = q * 4 + 0;
    if (v.y > 0.5f) cand = q * 4 + 1;
    if (v.z > 0.5f) cand = q * 4 + 2;
    if (v.w > 0.5f) cand = q * 4 + 3;

    if (cand >= 0) {
        out[row * VOCAB + g_table[cand]] = 1.0f;
    }
}

// ---------------------------------------------------------------------------
extern "C" void kernel_launch(void* const* d_in, const int* in_sizes, int n_in,
                              void* d_out, int out_size) {
    const float* inputs = nullptr;
    const float* W1 = nullptr;
    const float* b1 = nullptr;
    const float* W2 = nullptr;
    const float* b2 = nullptr;

    for (int i = 0; i < n_in; ++i) {
        switch (in_sizes[i]) {
            case 32 * 1024 * 64: inputs = (const float*)d_in[i]; break; // 2097152
            case 64 * 4096:      W1     = (const float*)d_in[i]; break; // 262144
            case 4096:           b1     = (const float*)d_in[i]; break;
            case 4096 * 128:     W2     = (const float*)d_in[i]; break; // 524288
            case 128:            b2     = (const float*)d_in[i]; break;
            default: break;
        }
    }

    partial_kernel<<<NBLK, 256>>>(W1, b1, W2, reinterpret_cast<float4*>(d_out));
    reduce_kernel<<<VOCAB, 128>>>(b2);

    const int n_f4 = (32 * 1024 * 64) / 4;            // 524288 float4
    scatter_kernel<<<n_f4 / 256, 256>>>(
        reinterpret_cast<const float4*>(inputs),
        reinterpret_cast<float*>(d_out));
}

// round 3
// speedup vs baseline: 2.4381x; 1.0066x over previous
#include <cuda_runtime.h>
#include <cuda_bf16.h>

// Problem constants (B=32, S=1024, V=64, H=4096)
#define VOCAB   64
#define HID     4096
#define UOUT    128          // 2*V
#define NBLK    128          // H-split blocks
#define HCHUNK  (HID / NBLK) // 32

// Per-token output index table: out_idx[t] = (scale_idx[t]*t + loc_idx[t]) mod 64
__device__ int    g_table[VOCAB];
// Partial logits scratch: part[t][b][uq], float4 u-quads
__device__ float4 g_part[VOCAB * NBLK * (UOUT / 4)];   // 4 MB

union F2u { unsigned long long u; float2 f; };

// Packed dual-FMA: d = a*b + d on two fp32 lanes (Blackwell f32x2 pipe).
__device__ __forceinline__ void ffma2(unsigned long long& d,
                                      const unsigned long long a,
                                      const unsigned long long b) {
    asm("fma.rn.f32x2 %0, %1, %2, %3;" : "=l"(d) : "l"(a), "l"(b), "l"(d));
}

// ---------------------------------------------------------------------------
// K1: partial logits + zero-fill of output.
// Block b owns H-chunk [b*32, b*32+32).
// net values are staged in smem PRE-DUPLICATED: nets2[t] is 16 float4s, the
// hb-th being {n_{2hb}, n_{2hb}, n_{2hb+1}, n_{2hb+1}} -> one broadcast
// LDS.128 feeds two h-steps of packed FFMA2 with zero repack instructions.
// Thread (uq, tg): u-quad uq (4 outputs), 8 tokens t0..t0+7.
// ---------------------------------------------------------------------------
__global__ __launch_bounds__(256, 1)
void partial_kernel(const float* __restrict__ W1, const float* __restrict__ b1,
                    const float* __restrict__ W2, float4* __restrict__ out_zero) {
    __shared__ float4 nets2[VOCAB * (HCHUNK / 2)];   // [t][hb]  8 KB
    __shared__ float4 w2s  [HCHUNK * (UOUT / 4)];    // [h][uq] 16 KB

    const int b   = blockIdx.x;
    const int tid = threadIdx.x;
    const int h0  = b * HCHUNK;

    // --- zero-fill this block's 64 KB slice of the output (overlaps compute) ---
    {
        const float4 z = make_float4(0.f, 0.f, 0.f, 0.f);
        float4* dst = out_zero + b * 4096;
        #pragma unroll
        for (int i = 0; i < 16; ++i) dst[tid + i * 256] = z;
    }

    // --- stage nets2: 512 jobs (t,f), each = relu(W1[t,h0+4f..+3]+b1) duplicated ---
    #pragma unroll
    for (int rep = 0; rep < 2; ++rep) {
        const int j = tid + rep * 256;
        const int t = j >> 3;          // 0..63
        const int f = j & 7;           // float4 within chunk
        float4 w = *reinterpret_cast<const float4*>(W1 + t * HID + h0 + f * 4);
        float4 c = *reinterpret_cast<const float4*>(b1 + h0 + f * 4);
        float n0 = fmaxf(w.x + c.x, 0.f);
        float n1 = fmaxf(w.y + c.y, 0.f);
        float n2 = fmaxf(w.z + c.z, 0.f);
        float n3 = fmaxf(w.w + c.w, 0.f);
        nets2[t * 16 + f * 2 + 0] = make_float4(n0, n0, n1, n1);
        nets2[t * 16 + f * 2 + 1] = make_float4(n2, n2, n3, n3);
    }
    // --- stage W2 chunk: 16 KB contiguous ---
    {
        const float4* src = reinterpret_cast<const float4*>(W2 + h0 * UOUT);
        #pragma unroll
        for (int i = 0; i < 4; ++i) w2s[tid + i * 256] = src[tid + i * 256];
    }
    __syncthreads();

    const int uq = tid & 31;           // u-quad 0..31
    const int t0 = (tid >> 5) * 8;     // 8 tokens per thread

    const ulonglong2* __restrict__ n2v = reinterpret_cast<const ulonglong2*>(nets2);
    const ulonglong2* __restrict__ w2v = reinterpret_cast<const ulonglong2*>(w2s);

    unsigned long long acc[8][2];
    #pragma unroll
    for (int t = 0; t < 8; ++t) { acc[t][0] = 0ull; acc[t][1] = 0ull; }

    #pragma unroll
    for (int hb = 0; hb < HCHUNK / 2; ++hb) {          // 2 h per step
        const ulonglong2 w0 = w2v[(2 * hb)     * 32 + uq];   // h = 2hb
        const ulonglong2 w1 = w2v[(2 * hb + 1) * 32 + uq];   // h = 2hb+1
        #pragma unroll
        for (int t = 0; t < 8; ++t) {
            const ulonglong2 nn = n2v[(t0 + t) * 16 + hb];   // {n,n},{n',n'}
            ffma2(acc[t][0], nn.x, w0.x);
            ffma2(acc[t][1], nn.x, w0.y);
            ffma2(acc[t][0], nn.y, w1.x);
            ffma2(acc[t][1], nn.y, w1.y);
        }
    }

    // --- write partials: part[t][b][uq], per-warp coalesced 512B rows ---
    #pragma unroll
    for (int t = 0; t < 8; ++t) {
        F2u a0, a1; a0.u = acc[t][0]; a1.u = acc[t][1];
        g_part[((t0 + t) * NBLK + b) * 32 + uq] =
            make_float4(a0.f.x, a0.f.y, a1.f.x, a1.f.y);
    }
}

// ---------------------------------------------------------------------------
// K2: reduce partials over the 128 blocks, add b2, argmax both halves,
// write g_table[t]. One block per token, 128 threads.
// ---------------------------------------------------------------------------
__global__ __launch_bounds__(128, 1)
void reduce_kernel(const float* __restrict__ b2) {
    __shared__ float red[4][UOUT];
    __shared__ float logits[UOUT];

    const int t    = blockIdx.x;
    const int tid  = threadIdx.x;
    const int warp = tid >> 5;
    const int lane = tid & 31;

    float4 acc = make_float4(0.f, 0.f, 0.f, 0.f);
    const float4* base = &g_part[(t * NBLK) * 32 + lane];
    #pragma unroll 8
    for (int b = warp * 32; b < warp * 32 + 32; ++b) {
        const float4 v = base[b * 32];
        acc.x += v.x; acc.y += v.y; acc.z += v.z; acc.w += v.w;
    }
    red[warp][lane * 4 + 0] = acc.x;
    red[warp][lane * 4 + 1] = acc.y;
    red[warp][lane * 4 + 2] = acc.z;
    red[warp][lane * 4 + 3] = acc.w;
    __syncthreads();

    if (tid < UOUT) {
        logits[tid] = red[0][tid] + red[1][tid] + red[2][tid] + red[3][tid] + b2[tid];
    }
    __syncthreads();

    if (tid == 0) {
        // jnp.argmax keeps the FIRST max -> strict '>' comparison.
        int   li = 0; float lm = logits[0];
        #pragma unroll
        for (int k = 1; k < VOCAB; ++k) if (logits[k] > lm) { lm = logits[k]; li = k; }
        int   si = 0; float sm = logits[VOCAB];
        #pragma unroll
        for (int k = 1; k < VOCAB; ++k) if (logits[VOCAB + k] > sm) { sm = logits[VOCAB + k]; si = k; }
        // loc = first half, scale = second half (jnp.split order)
        g_table[t] = (si * t + li) & (VOCAB - 1);
    }
}

// ---------------------------------------------------------------------------
// K3: scatter pass, MLP=4. Output pre-zeroed in K1; each thread reads 4
// independent float4s of the one-hot input (batched loads -> deep L1tex
// queue) and writes a single 1.0f per hit row.
// ---------------------------------------------------------------------------
#define TOTAL_F4 (32 * 1024 * 64 / 4)   // 524288
#define SC_STRIDE (TOTAL_F4 / 4)        // 131072

__global__ __launch_bounds__(256)
void scatter_kernel(const float4* __restrict__ in, float* __restrict__ out) {
    const int base = blockIdx.x * 256 + threadIdx.x;

    float4 v[4];
    #pragma unroll
    for (int k = 0; k < 4; ++k) v[k] = in[base + k * SC_STRIDE];   // 4 in-flight LDG.128

    #pragma unroll
    for (int k = 0; k < 4; ++k) {
        const int gid = base + k * SC_STRIDE;
        const int q   = gid & 15;
        int cand = -1;
        if (v[k].x > 0.5f) cand = q * 4 + 0;
        if (v[k].y > 0.5f) cand = q * 4 + 1;
        if (v[k].z > 0.5f) cand = q * 4 + 2;
        if (v[k].w > 0.5f) cand = q * 4 + 3;
        if (cand >= 0) {
            out[(gid >> 4) * VOCAB + g_table[cand]] = 1.0f;
        }
    }
}

// ---------------------------------------------------------------------------
extern "C" void kernel_launch(void* const* d_in, const int* in_sizes, int n_in,
                              void* d_out, int out_size) {
    const float* inputs = nullptr;
    const float* W1 = nullptr;
    const float* b1 = nullptr;
    const float* W2 = nullptr;
    const float* b2 = nullptr;

    for (int i = 0; i < n_in; ++i) {
        switch (in_sizes[i]) {
            case 32 * 1024 * 64: inputs = (const float*)d_in[i]; break; // 2097152
            case 64 * 4096:      W1     = (const float*)d_in[i]; break; // 262144
            case 4096:           b1     = (const float*)d_in[i]; break;
            case 4096 * 128:     W2     = (const float*)d_in[i]; break; // 524288
            case 128:            b2     = (const float*)d_in[i]; break;
            default: break;
        }
    }

    partial_kernel<<<NBLK, 256>>>(W1, b1, W2, reinterpret_cast<float4*>(d_out));
    reduce_kernel<<<VOCAB, 128>>>(b2);
    scatter_kernel<<<TOTAL_F4 / (256 * 4), 256>>>(
        reinterpret_cast<const float4*>(inputs),
        reinterpret_cast<float*>(d_out));
}

// round 4
// speedup vs baseline: 2.4489x; 1.0044x over previous
#include <cuda_runtime.h>
#include <cuda_bf16.h>

// Problem constants (B=32, S=1024, V=64, H=4096)
#define VOCAB   64
#define HID     4096
#define UOUT    128          // 2*V
#define NBLK    128          // H-split blocks
#define HCHUNK  (HID / NBLK) // 32

// Per-token output index table: out_idx[t] = (scale_idx[t]*t + loc_idx[t]) mod 64
__device__ int    g_table[VOCAB];
// Partial logits scratch: part[t][b][uq], float4 u-quads
__device__ float4 g_part[VOCAB * NBLK * (UOUT / 4)];   // 4 MB

union F2u { unsigned long long u; float2 f; };

// Packed dual-FMA: d = a*b + d on two fp32 lanes.
__device__ __forceinline__ void ffma2(unsigned long long& d,
                                      const unsigned long long a,
                                      const unsigned long long b) {
    asm("fma.rn.f32x2 %0, %1, %2, %3;" : "=l"(d) : "l"(a), "l"(b), "l"(d));
}

// ---------------------------------------------------------------------------
// K1: partial logits + zero-fill of output. 512 threads (16 warps/SM).
// Block b owns H-chunk [b*32, b*32+32).
// Staging LDGs are issued FIRST so their DRAM latency overlaps the zero-fill
// stores. nets2 staged pre-duplicated {n,n,n',n'} so one broadcast LDS.128
// feeds two h-steps of packed FFMA2.
// Thread (uq, group): u-quad uq, 4 tokens t0..t0+3.
// ---------------------------------------------------------------------------
__global__ __launch_bounds__(512, 1)
void partial_kernel(const float* __restrict__ W1, const float* __restrict__ b1,
                    const float* __restrict__ W2, float4* __restrict__ out_zero) {
    __shared__ float4 nets2[VOCAB * (HCHUNK / 2)];   // [t][hb]  8 KB
    __shared__ float4 w2s  [HCHUNK * (UOUT / 4)];    // [h][uq] 16 KB

    const int b   = blockIdx.x;
    const int tid = threadIdx.x;
    const int h0  = b * HCHUNK;

    // --- issue all staging LDGs first (latency overlaps zero-fill below) ---
    const int jt = tid >> 3;           // token 0..63  (512 jobs exactly)
    const int jf = tid & 7;            // float4 within chunk
    const float4 w1v = *reinterpret_cast<const float4*>(W1 + jt * HID + h0 + jf * 4);
    const float4 b1v = *reinterpret_cast<const float4*>(b1 + h0 + jf * 4);
    const float4* __restrict__ w2src = reinterpret_cast<const float4*>(W2 + h0 * UOUT);
    const float4 w2a = w2src[tid];
    const float4 w2b = w2src[tid + 512];

    // --- zero-fill this block's 64 KB slice of the output ---
    {
        const float4 z = make_float4(0.f, 0.f, 0.f, 0.f);
        float4* dst = out_zero + b * 4096;
        #pragma unroll
        for (int i = 0; i < 8; ++i) dst[tid + i * 512] = z;
    }

    // --- commit staging to smem ---
    {
        float n0 = fmaxf(w1v.x + b1v.x, 0.f);
        float n1 = fmaxf(w1v.y + b1v.y, 0.f);
        float n2 = fmaxf(w1v.z + b1v.z, 0.f);
        float n3 = fmaxf(w1v.w + b1v.w, 0.f);
        nets2[jt * 16 + jf * 2 + 0] = make_float4(n0, n0, n1, n1);
        nets2[jt * 16 + jf * 2 + 1] = make_float4(n2, n2, n3, n3);
        w2s[tid]       = w2a;
        w2s[tid + 512] = w2b;
    }
    __syncthreads();

    const int uq = tid & 31;           // u-quad 0..31
    const int t0 = (tid >> 5) * 4;     // 4 tokens per thread (16 groups)

    const ulonglong2* __restrict__ n2v = reinterpret_cast<const ulonglong2*>(nets2);
    const ulonglong2* __restrict__ w2v = reinterpret_cast<const ulonglong2*>(w2s);

    unsigned long long acc[4][2];
    #pragma unroll
    for (int t = 0; t < 4; ++t) { acc[t][0] = 0ull; acc[t][1] = 0ull; }

    #pragma unroll
    for (int hb = 0; hb < HCHUNK / 2; ++hb) {              // 2 h per step
        const ulonglong2 w0 = w2v[(2 * hb)     * 32 + uq]; // h = 2hb
        const ulonglong2 w1 = w2v[(2 * hb + 1) * 32 + uq]; // h = 2hb+1
        #pragma unroll
        for (int t = 0; t < 4; ++t) {
            const ulonglong2 nn = n2v[(t0 + t) * 16 + hb]; // broadcast {n,n},{n',n'}
            ffma2(acc[t][0], nn.x, w0.x);
            ffma2(acc[t][1], nn.x, w0.y);
            ffma2(acc[t][0], nn.y, w1.x);
            ffma2(acc[t][1], nn.y, w1.y);
        }
    }

    // --- write partials: part[t][b][uq], per-warp coalesced 512B rows ---
    #pragma unroll
    for (int t = 0; t < 4; ++t) {
        F2u a0, a1; a0.u = acc[t][0]; a1.u = acc[t][1];
        g_part[((t0 + t) * NBLK + b) * 32 + uq] =
            make_float4(a0.f.x, a0.f.y, a1.f.x, a1.f.y);
    }
}

// ---------------------------------------------------------------------------
// K2: reduce partials over the 128 H-blocks, add b2, argmax both halves.
// One block per token, 256 threads (8 warps x 16 b's each).
// ---------------------------------------------------------------------------
__global__ __launch_bounds__(256, 1)
void reduce_kernel(const float* __restrict__ b2) {
    __shared__ float red[8][UOUT];
    __shared__ float logits[UOUT];

    const int t    = blockIdx.x;
    const int tid  = threadIdx.x;
    const int warp = tid >> 5;
    const int lane = tid & 31;

    float4 acc = make_float4(0.f, 0.f, 0.f, 0.f);
    const float4* base = &g_part[(t * NBLK) * 32 + lane];
    #pragma unroll 8
    for (int b = warp * 16; b < warp * 16 + 16; ++b) {
        const float4 v = base[b * 32];
        acc.x += v.x; acc.y += v.y; acc.z += v.z; acc.w += v.w;
    }
    red[warp][lane * 4 + 0] = acc.x;
    red[warp][lane * 4 + 1] = acc.y;
    red[warp][lane * 4 + 2] = acc.z;
    red[warp][lane * 4 + 3] = acc.w;
    __syncthreads();

    if (tid < UOUT) {
        float s = b2[tid];
        #pragma unroll
        for (int w = 0; w < 8; ++w) s += red[w][tid];
        logits[tid] = s;
    }
    __syncthreads();

    if (tid == 0) {
        // jnp.argmax keeps the FIRST max -> strict '>' comparison.
        int   li = 0; float lm = logits[0];
        #pragma unroll
        for (int k = 1; k < VOCAB; ++k) if (logits[k] > lm) { lm = logits[k]; li = k; }
        int   si = 0; float sm = logits[VOCAB];
        #pragma unroll
        for (int k = 1; k < VOCAB; ++k) if (logits[VOCAB + k] > sm) { sm = logits[VOCAB + k]; si = k; }
        // loc = first half, scale = second half (jnp.split order)
        g_table[t] = (si * t + li) & (VOCAB - 1);
    }
}

// ---------------------------------------------------------------------------
// K3: scatter pass, MLP=4. Output pre-zeroed in K1; each thread reads 4
// independent float4s of the one-hot input and writes one 1.0f per hit row.
// ---------------------------------------------------------------------------
#define TOTAL_F4 (32 * 1024 * 64 / 4)   // 524288
#define SC_STRIDE (TOTAL_F4 / 4)        // 131072

__global__ __launch_bounds__(256)
void scatter_kernel(const float4* __restrict__ in, float* __restrict__ out) {
    const int base = blockIdx.x * 256 + threadIdx.x;

    float4 v[4];
    #pragma unroll
    for (int k = 0; k < 4; ++k) v[k] = in[base + k * SC_STRIDE];   // 4 in-flight LDG.128

    #pragma unroll
    for (int k = 0; k < 4; ++k) {
        const int gid = base + k * SC_STRIDE;
        const int q   = gid & 15;
        int cand = -1;
        if (v[k].x > 0.5f) cand = q * 4 + 0;
        if (v[k].y > 0.5f) cand = q * 4 + 1;
        if (v[k].z > 0.5f) cand = q * 4 + 2;
        if (v[k].w > 0.5f) cand = q * 4 + 3;
        if (cand >= 0) {
            out[(gid >> 4) * VOCAB + g_table[cand]] = 1.0f;
        }
    }
}

// ---------------------------------------------------------------------------
extern "C" void kernel_launch(void* const* d_in, const int* in_sizes, int n_in,
                              void* d_out, int out_size) {
    const float* inputs = nullptr;
    const float* W1 = nullptr;
    const float* b1 = nullptr;
    const float* W2 = nullptr;
    const float* b2 = nullptr;

    for (int i = 0; i < n_in; ++i) {
        switch (in_sizes[i]) {
            case 32 * 1024 * 64: inputs = (const float*)d_in[i]; break; // 2097152
            case 64 * 4096:      W1     = (const float*)d_in[i]; break; // 262144
            case 4096:           b1     = (const float*)d_in[i]; break;
            case 4096 * 128:     W2     = (const float*)d_in[i]; break; // 524288
            case 128:            b2     = (const float*)d_in[i]; break;
            default: break;
        }
    }

    partial_kernel<<<NBLK, 512>>>(W1, b1, W2, reinterpret_cast<float4*>(d_out));
    reduce_kernel<<<VOCAB, 256>>>(b2);
    scatter_kernel<<<TOTAL_F4 / (256 * 4), 256>>>(
        reinterpret_cast<const float4*>(inputs),
        reinterpret_cast<float*>(d_out));
}